// round 13
// baseline (speedup 1.0000x reference)
#include <cuda_runtime.h>

#define L    64      // steps per chunk
#define KCH  256     // chunks per batch (T / L)
#define MAXB 256
#define OVLG 2       // overlap groups (8 warm-up steps)
#define CPB  128     // chunks (threads) per block
#define RS   36      // smem row stride in floats (32 data + 4 pad)

__device__ float g_c  [MAXB * KCH];   // per-chunk log-growth
__device__ float g_sp [MAXB * KCH];   // per-chunk score partial
__device__ int   g_cnt[MAXB * KCH];   // per-chunk masked count (t>=1)
__device__ float g_nf [MAXB * 8];     // normalized final alpha direction

// ---- packed f32x2 helpers ---------------------------------------------------
__device__ __forceinline__ unsigned long long pk2(float lo, float hi) {
    unsigned long long r;
    asm("mov.b64 %0, {%1, %2};" : "=l"(r) : "f"(lo), "f"(hi));
    return r;
}
__device__ __forceinline__ void upk2(unsigned long long v, float& lo, float& hi) {
    asm("mov.b64 {%0, %1}, %2;" : "=f"(lo), "=f"(hi) : "l"(v));
}
__device__ __forceinline__ unsigned long long mul2(unsigned long long a, unsigned long long b) {
    unsigned long long r;
    asm("mul.rn.f32x2 %0, %1, %2;" : "=l"(r) : "l"(a), "l"(b));
    return r;
}
__device__ __forceinline__ unsigned long long fma2(unsigned long long a, unsigned long long b,
                                                   unsigned long long c) {
    unsigned long long r;
    asm("fma.rn.f32x2 %0, %1, %2, %3;" : "=l"(r) : "l"(a), "l"(b), "l"(c));
    return r;
}

// v <- (v^T M) ∘ exp(e)
__device__ __forceinline__ void vstep(float v[8], const unsigned long long M2[8][4],
                                      const float e[8])
{
    unsigned long long ev0 = pk2(__expf(e[0]), __expf(e[1]));
    unsigned long long ev1 = pk2(__expf(e[2]), __expf(e[3]));
    unsigned long long ev2 = pk2(__expf(e[4]), __expf(e[5]));
    unsigned long long ev3 = pk2(__expf(e[6]), __expf(e[7]));

    unsigned long long vb = pk2(v[0], v[0]);
    unsigned long long a0 = mul2(vb, M2[0][0]);
    unsigned long long a1 = mul2(vb, M2[0][1]);
    unsigned long long a2 = mul2(vb, M2[0][2]);
    unsigned long long a3 = mul2(vb, M2[0][3]);
#pragma unroll
    for (int i = 1; i < 8; i++) {
        vb = pk2(v[i], v[i]);
        a0 = fma2(vb, M2[i][0], a0);
        a1 = fma2(vb, M2[i][1], a1);
        a2 = fma2(vb, M2[i][2], a2);
        a3 = fma2(vb, M2[i][3], a3);
    }
    a0 = mul2(a0, ev0);
    a1 = mul2(a1, ev1);
    a2 = mul2(a2, ev2);
    a3 = mul2(a3, ev3);
    upk2(a0, v[0], v[1]);
    upk2(a1, v[2], v[3]);
    upk2(a2, v[4], v[5]);
    upk2(a3, v[6], v[7]);
}

// ---------------------------------------------------------------------------
// Kernel 1: R12 champion chunk kernel + __launch_bounds__(CPB, 3) to force
// 3 blocks/SM (12 warps/SM instead of 8). No other changes.
// ---------------------------------------------------------------------------
__global__ void __launch_bounds__(CPB, 3) crf_chunk_vec(
    const float* __restrict__ em,
    const int* __restrict__ tags,
    const int* __restrict__ mask,
    const float* __restrict__ trans,
    const float* __restrict__ startt,
    int B, int T)
{
    __shared__ float sE[2][CPB * RS];

    int tid = threadIdx.x;
    int b   = blockIdx.x >> 1;
    int k0  = (blockIdx.x & 1) * CPB;
    int k   = k0 + tid;
    size_t bT = (size_t)b * T;
    const float* emB = em + bT * 8;

    unsigned long long M2[8][4];
#pragma unroll
    for (int i = 0; i < 8; i++)
#pragma unroll
        for (int jj = 0; jj < 4; jj++)
            M2[i][jj] = pk2(__expf(__ldg(&trans[i * 8 + 2 * jj])),
                            __expf(__ldg(&trans[i * 8 + 2 * jj + 1])));

    float v[8];
#pragma unroll
    for (int j = 0; j < 8; j++) v[j] = 0.125f;

    float c = 0.0f, sp = 0.0f;
    int mcnt = 0;
    int pv = __ldg(&tags[bT + (k > 0 ? k * L - 1 : 0)]);

    float4 stg[8];
    // preload first tile (g = -OVLG)
#pragma unroll
    for (int m = 0; m < 8; m++) {
        int idx = m * CPB + tid;
        int r   = idx >> 3;
        int qq  = idx & 7;
        int tr  = (k0 + r) * L + 4 * (-OVLG);
        if (tr < 0) tr = 0;
        stg[m] = __ldg((const float4*)(emB + (size_t)tr * 8) + qq);
    }
#pragma unroll
    for (int m = 0; m < 8; m++) {
        int idx = m * CPB + tid;
        *((float4*)(sE[0] + (idx >> 3) * RS) + (idx & 7)) = stg[m];
    }
    __syncthreads();

    for (int g = -OVLG; g < L / 4; g++) {
        int cur = (g + OVLG) & 1;

        // issue next tile's LDGs before compute (latency hidden under compute)
        bool more = (g + 1 < L / 4);
        if (more) {
#pragma unroll
            for (int m = 0; m < 8; m++) {
                int idx = m * CPB + tid;
                int r   = idx >> 3;
                int qq  = idx & 7;
                int tr  = (k0 + r) * L + 4 * (g + 1);
                if (tr < 0) tr = 0;
                stg[m] = __ldg((const float4*)(emB + (size_t)tr * 8) + qq);
            }
        }

        int tb = k * L + 4 * g;
        const float* erow = sE[cur] + tid * RS;

        if (g == 0) {
            if (k == 0) {
                float e0[8];
                *(float4*)(e0)     = *((const float4*)erow);
                *(float4*)(e0 + 4) = *((const float4*)erow + 1);
                float s = 0.0f;
#pragma unroll
                for (int j = 0; j < 8; j++) {
                    v[j] = __expf(__ldg(&startt[j]) + e0[j]);
                    s += v[j];
                }
                c = __logf(s);
                float r = __fdividef(1.0f, s);
#pragma unroll
                for (int j = 0; j < 8; j++) v[j] *= r;
            } else {
                float s = v[0]+v[1]+v[2]+v[3]+v[4]+v[5]+v[6]+v[7];
                float r = __fdividef(1.0f, s);
                c = 0.0f;
#pragma unroll
                for (int j = 0; j < 8; j++) v[j] *= r;
            }
        }

        if (g >= 0) {
            int4 tg4 = __ldg((const int4*)(tags + bT + tb));
            int4 mk4 = __ldg((const int4*)(mask + bT + tb));
            int tgA[4] = {tg4.x, tg4.y, tg4.z, tg4.w};
            int mkA[4] = {mk4.x, mk4.y, mk4.z, mk4.w};
#pragma unroll
            for (int q = 0; q < 4; q++) {
                float e[8];
                *(float4*)(e)     = *((const float4*)erow + 2 * q);
                *(float4*)(e + 4) = *((const float4*)erow + 2 * q + 1);
                int tg = tgA[q];
                if (mkA[q] && (tb + q >= 1)) {
                    vstep(v, M2, e);
                    float es = e[0];
#pragma unroll
                    for (int j = 1; j < 8; j++) es = (tg == j) ? e[j] : es;
                    sp += es + __ldg(&trans[pv * 8 + tg]);
                    mcnt++;
                }
                pv = tg;
            }
        } else if (tb >= 0) {   // warm-up (k>0 only)
            int4 mk4 = __ldg((const int4*)(mask + bT + tb));
            int mkA[4] = {mk4.x, mk4.y, mk4.z, mk4.w};
#pragma unroll
            for (int q = 0; q < 4; q++) {
                float e[8];
                *(float4*)(e)     = *((const float4*)erow + 2 * q);
                *(float4*)(e + 4) = *((const float4*)erow + 2 * q + 1);
                if (mkA[q]) vstep(v, M2, e);
            }
        }

        // group-end rescale
        {
            float s = v[0]+v[1]+v[2]+v[3]+v[4]+v[5]+v[6]+v[7];
            float r = __fdividef(1.0f, s);
            c += __logf(s);
#pragma unroll
            for (int j = 0; j < 8; j++) v[j] *= r;
        }

        // store next tile into the alternate buffer, then one sync
        if (more) {
#pragma unroll
            for (int m = 0; m < 8; m++) {
                int idx = m * CPB + tid;
                *((float4*)(sE[cur ^ 1] + (idx >> 3) * RS) + (idx & 7)) = stg[m];
            }
            __syncthreads();
        }
    }

    size_t gidx = (size_t)b * KCH + k;
    g_c  [gidx] = c;
    g_sp [gidx] = sp;
    g_cnt[gidx] = mcnt;
    if (k == KCH - 1) {
#pragma unroll
        for (int j = 0; j < 8; j++) g_nf[b * 8 + j] = v[j];
    }
}

// ---------------------------------------------------------------------------
// Kernel 2: warp per batch. Lanes each sum 8 chunks of (c, sp, cnt), warp
// reduce, lane 0 adds end term and emits NLL.
// ---------------------------------------------------------------------------
__global__ void __launch_bounds__(256) crf_final(
    const float* __restrict__ em,
    const int* __restrict__ tags,
    const int* __restrict__ mask,
    const float* __restrict__ startt,
    const float* __restrict__ endt,
    float* __restrict__ out,
    int B, int T)
{
    int w    = (blockIdx.x * blockDim.x + threadIdx.x) >> 5;
    int lane = threadIdx.x & 31;
    if (w >= B) return;
    const int b = w;
    const unsigned FULL = 0xffffffffu;
    size_t bK = (size_t)b * KCH;

    float c = 0.0f, sp = 0.0f;
    int cnt = 0;
#pragma unroll
    for (int q = 0; q < 8; q++) {
        c   += __ldg(&g_c  [bK + lane + 32 * q]);
        sp  += __ldg(&g_sp [bK + lane + 32 * q]);
        cnt += __ldg(&g_cnt[bK + lane + 32 * q]);
    }
#pragma unroll
    for (int off = 16; off >= 1; off >>= 1) {
        c   += __shfl_xor_sync(FULL, c,   off);
        sp  += __shfl_xor_sync(FULL, sp,  off);
        cnt += __shfl_xor_sync(FULL, cnt, off);
    }

    if (lane == 0) {
        size_t bT = (size_t)b * T;
        float vsum = 0.0f;
#pragma unroll
        for (int j = 0; j < 8; j++)
            vsum += g_nf[b * 8 + j] * __expf(__ldg(&endt[j]));
        float logZ = c + __logf(vsum);

        cnt += (__ldg(&mask[bT]) != 0) ? 1 : 0;
        int last_valid = cnt - 1;
        int tag0  = __ldg(&tags[bT]);
        int lastt = __ldg(&tags[bT + last_valid]);
        float score = __ldg(&startt[tag0]) + __ldg(&em[bT * 8 + tag0])
                    + sp + __ldg(&endt[lastt]);
        out[b] = logZ - score;
    }
}

// ---------------------------------------------------------------------------
extern "C" void kernel_launch(void* const* d_in, const int* in_sizes, int n_in,
                              void* d_out, int out_size)
{
    const float* em     = (const float*)d_in[0];
    const int*   tags   = (const int*)d_in[1];
    const int*   mask   = (const int*)d_in[2];
    const float* trans  = (const float*)d_in[3];
    const float* startt = (const float*)d_in[4];
    const float* endt   = (const float*)d_in[5];

    int B = out_size;                 // 256
    int T = in_sizes[0] / (B * 8);    // 16384 (= KCH * L)

    int nblocks = B * (KCH / CPB);    // 512
    crf_chunk_vec<<<nblocks, CPB>>>(em, tags, mask, trans, startt, B, T);

    crf_final<<<(B * 32 + 255) / 256, 256>>>(em, tags, mask, startt, endt,
                                             (float*)d_out, B, T);
}

// round 14
// speedup vs baseline: 1.0187x; 1.0187x over previous
#include <cuda_runtime.h>

#define L    64      // steps per chunk
#define KCH  256     // chunks per batch (T / L)
#define MAXB 256
#define OVLG 2       // overlap groups (8 warm-up steps)
#define CPB  128     // chunks (threads) per block
#define RS   36      // smem row stride in floats (32 data + 4 pad)

__device__ float g_c  [MAXB * KCH];   // per-chunk log-growth
__device__ float g_sp [MAXB * KCH];   // per-chunk score partial
__device__ int   g_cnt[MAXB * KCH];   // per-chunk masked count (t>=1)
__device__ float g_nf [MAXB * 8];     // normalized final alpha direction

// ---- packed f32x2 helpers ---------------------------------------------------
__device__ __forceinline__ unsigned long long pk2(float lo, float hi) {
    unsigned long long r;
    asm("mov.b64 %0, {%1, %2};" : "=l"(r) : "f"(lo), "f"(hi));
    return r;
}
__device__ __forceinline__ void upk2(unsigned long long v, float& lo, float& hi) {
    asm("mov.b64 {%0, %1}, %2;" : "=f"(lo), "=f"(hi) : "l"(v));
}
__device__ __forceinline__ unsigned long long mul2(unsigned long long a, unsigned long long b) {
    unsigned long long r;
    asm("mul.rn.f32x2 %0, %1, %2;" : "=l"(r) : "l"(a), "l"(b));
    return r;
}
__device__ __forceinline__ unsigned long long fma2(unsigned long long a, unsigned long long b,
                                                   unsigned long long c) {
    unsigned long long r;
    asm("fma.rn.f32x2 %0, %1, %2, %3;" : "=l"(r) : "l"(a), "l"(b), "l"(c));
    return r;
}

// v <- (v^T M) ∘ exp(e)
__device__ __forceinline__ void vstep(float v[8], const unsigned long long M2[8][4],
                                      const float e[8])
{
    unsigned long long ev0 = pk2(__expf(e[0]), __expf(e[1]));
    unsigned long long ev1 = pk2(__expf(e[2]), __expf(e[3]));
    unsigned long long ev2 = pk2(__expf(e[4]), __expf(e[5]));
    unsigned long long ev3 = pk2(__expf(e[6]), __expf(e[7]));

    unsigned long long vb = pk2(v[0], v[0]);
    unsigned long long a0 = mul2(vb, M2[0][0]);
    unsigned long long a1 = mul2(vb, M2[0][1]);
    unsigned long long a2 = mul2(vb, M2[0][2]);
    unsigned long long a3 = mul2(vb, M2[0][3]);
#pragma unroll
    for (int i = 1; i < 8; i++) {
        vb = pk2(v[i], v[i]);
        a0 = fma2(vb, M2[i][0], a0);
        a1 = fma2(vb, M2[i][1], a1);
        a2 = fma2(vb, M2[i][2], a2);
        a3 = fma2(vb, M2[i][3], a3);
    }
    a0 = mul2(a0, ev0);
    a1 = mul2(a1, ev1);
    a2 = mul2(a2, ev2);
    a3 = mul2(a3, ev3);
    upk2(a0, v[0], v[1]);
    upk2(a1, v[2], v[3]);
    upk2(a2, v[4], v[5]);
    upk2(a3, v[6], v[7]);
}

// ---------------------------------------------------------------------------
// Kernel 1: R12 champion chunk kernel (no occupancy cap) + tags/mask
// prefetched one group ahead alongside the emission prefetch.
// ---------------------------------------------------------------------------
__global__ void __launch_bounds__(CPB) crf_chunk_vec(
    const float* __restrict__ em,
    const int* __restrict__ tags,
    const int* __restrict__ mask,
    const float* __restrict__ trans,
    const float* __restrict__ startt,
    int B, int T)
{
    __shared__ float sE[2][CPB * RS];

    int tid = threadIdx.x;
    int b   = blockIdx.x >> 1;
    int k0  = (blockIdx.x & 1) * CPB;
    int k   = k0 + tid;
    size_t bT = (size_t)b * T;
    const float* emB = em + bT * 8;

    unsigned long long M2[8][4];
#pragma unroll
    for (int i = 0; i < 8; i++)
#pragma unroll
        for (int jj = 0; jj < 4; jj++)
            M2[i][jj] = pk2(__expf(__ldg(&trans[i * 8 + 2 * jj])),
                            __expf(__ldg(&trans[i * 8 + 2 * jj + 1])));

    float v[8];
#pragma unroll
    for (int j = 0; j < 8; j++) v[j] = 0.125f;

    float c = 0.0f, sp = 0.0f;
    int mcnt = 0;
    int pv = __ldg(&tags[bT + (k > 0 ? k * L - 1 : 0)]);

    float4 stg[8];
    // preload first tile (g = -OVLG)
#pragma unroll
    for (int m = 0; m < 8; m++) {
        int idx = m * CPB + tid;
        int r   = idx >> 3;
        int qq  = idx & 7;
        int tr  = (k0 + r) * L + 4 * (-OVLG);
        if (tr < 0) tr = 0;
        stg[m] = __ldg((const float4*)(emB + (size_t)tr * 8) + qq);
    }
#pragma unroll
    for (int m = 0; m < 8; m++) {
        int idx = m * CPB + tid;
        *((float4*)(sE[0] + (idx >> 3) * RS) + (idx & 7)) = stg[m];
    }
    __syncthreads();

    // prefetch tags/mask for the first group
    int4 tg4n, mk4n;
    {
        int tb = k * L + 4 * (-OVLG);
        int tc = tb < 0 ? 0 : tb;
        tg4n = __ldg((const int4*)(tags + bT + tc));
        mk4n = __ldg((const int4*)(mask + bT + tc));
    }

    for (int g = -OVLG; g < L / 4; g++) {
        int cur = (g + OVLG) & 1;

        int4 tg4 = tg4n;
        int4 mk4 = mk4n;

        // issue next group's loads before compute (latency hidden under compute)
        bool more = (g + 1 < L / 4);
        if (more) {
#pragma unroll
            for (int m = 0; m < 8; m++) {
                int idx = m * CPB + tid;
                int r   = idx >> 3;
                int qq  = idx & 7;
                int tr  = (k0 + r) * L + 4 * (g + 1);
                if (tr < 0) tr = 0;
                stg[m] = __ldg((const float4*)(emB + (size_t)tr * 8) + qq);
            }
            int tb = k * L + 4 * (g + 1);
            int tc = tb < 0 ? 0 : tb;
            tg4n = __ldg((const int4*)(tags + bT + tc));
            mk4n = __ldg((const int4*)(mask + bT + tc));
        }

        int tb = k * L + 4 * g;
        const float* erow = sE[cur] + tid * RS;

        if (g == 0) {
            if (k == 0) {
                float e0[8];
                *(float4*)(e0)     = *((const float4*)erow);
                *(float4*)(e0 + 4) = *((const float4*)erow + 1);
                float s = 0.0f;
#pragma unroll
                for (int j = 0; j < 8; j++) {
                    v[j] = __expf(__ldg(&startt[j]) + e0[j]);
                    s += v[j];
                }
                c = __logf(s);
                float r = __fdividef(1.0f, s);
#pragma unroll
                for (int j = 0; j < 8; j++) v[j] *= r;
            } else {
                float s = v[0]+v[1]+v[2]+v[3]+v[4]+v[5]+v[6]+v[7];
                float r = __fdividef(1.0f, s);
                c = 0.0f;
#pragma unroll
                for (int j = 0; j < 8; j++) v[j] *= r;
            }
        }

        if (g >= 0) {
            int tgA[4] = {tg4.x, tg4.y, tg4.z, tg4.w};
            int mkA[4] = {mk4.x, mk4.y, mk4.z, mk4.w};
#pragma unroll
            for (int q = 0; q < 4; q++) {
                float e[8];
                *(float4*)(e)     = *((const float4*)erow + 2 * q);
                *(float4*)(e + 4) = *((const float4*)erow + 2 * q + 1);
                int tg = tgA[q];
                if (mkA[q] && (tb + q >= 1)) {
                    vstep(v, M2, e);
                    float es = e[0];
#pragma unroll
                    for (int j = 1; j < 8; j++) es = (tg == j) ? e[j] : es;
                    sp += es + __ldg(&trans[pv * 8 + tg]);
                    mcnt++;
                }
                pv = tg;
            }
        } else if (tb >= 0) {   // warm-up (k>0 only)
            int mkA[4] = {mk4.x, mk4.y, mk4.z, mk4.w};
#pragma unroll
            for (int q = 0; q < 4; q++) {
                float e[8];
                *(float4*)(e)     = *((const float4*)erow + 2 * q);
                *(float4*)(e + 4) = *((const float4*)erow + 2 * q + 1);
                if (mkA[q]) vstep(v, M2, e);
            }
        }

        // group-end rescale
        {
            float s = v[0]+v[1]+v[2]+v[3]+v[4]+v[5]+v[6]+v[7];
            float r = __fdividef(1.0f, s);
            c += __logf(s);
#pragma unroll
            for (int j = 0; j < 8; j++) v[j] *= r;
        }

        // store next tile into the alternate buffer, then one sync
        if (more) {
#pragma unroll
            for (int m = 0; m < 8; m++) {
                int idx = m * CPB + tid;
                *((float4*)(sE[cur ^ 1] + (idx >> 3) * RS) + (idx & 7)) = stg[m];
            }
            __syncthreads();
        }
    }

    size_t gidx = (size_t)b * KCH + k;
    g_c  [gidx] = c;
    g_sp [gidx] = sp;
    g_cnt[gidx] = mcnt;
    if (k == KCH - 1) {
#pragma unroll
        for (int j = 0; j < 8; j++) g_nf[b * 8 + j] = v[j];
    }
}

// ---------------------------------------------------------------------------
// Kernel 2: warp per batch. Lanes each sum 8 chunks of (c, sp, cnt), warp
// reduce, lane 0 adds end term and emits NLL.
// ---------------------------------------------------------------------------
__global__ void __launch_bounds__(256) crf_final(
    const float* __restrict__ em,
    const int* __restrict__ tags,
    const int* __restrict__ mask,
    const float* __restrict__ startt,
    const float* __restrict__ endt,
    float* __restrict__ out,
    int B, int T)
{
    int w    = (blockIdx.x * blockDim.x + threadIdx.x) >> 5;
    int lane = threadIdx.x & 31;
    if (w >= B) return;
    const int b = w;
    const unsigned FULL = 0xffffffffu;
    size_t bK = (size_t)b * KCH;

    float c = 0.0f, sp = 0.0f;
    int cnt = 0;
#pragma unroll
    for (int q = 0; q < 8; q++) {
        c   += __ldg(&g_c  [bK + lane + 32 * q]);
        sp  += __ldg(&g_sp [bK + lane + 32 * q]);
        cnt += __ldg(&g_cnt[bK + lane + 32 * q]);
    }
#pragma unroll
    for (int off = 16; off >= 1; off >>= 1) {
        c   += __shfl_xor_sync(FULL, c,   off);
        sp  += __shfl_xor_sync(FULL, sp,  off);
        cnt += __shfl_xor_sync(FULL, cnt, off);
    }

    if (lane == 0) {
        size_t bT = (size_t)b * T;
        float vsum = 0.0f;
#pragma unroll
        for (int j = 0; j < 8; j++)
            vsum += g_nf[b * 8 + j] * __expf(__ldg(&endt[j]));
        float logZ = c + __logf(vsum);

        cnt += (__ldg(&mask[bT]) != 0) ? 1 : 0;
        int last_valid = cnt - 1;
        int tag0  = __ldg(&tags[bT]);
        int lastt = __ldg(&tags[bT + last_valid]);
        float score = __ldg(&startt[tag0]) + __ldg(&em[bT * 8 + tag0])
                    + sp + __ldg(&endt[lastt]);
        out[b] = logZ - score;
    }
}

// ---------------------------------------------------------------------------
extern "C" void kernel_launch(void* const* d_in, const int* in_sizes, int n_in,
                              void* d_out, int out_size)
{
    const float* em     = (const float*)d_in[0];
    const int*   tags   = (const int*)d_in[1];
    const int*   mask   = (const int*)d_in[2];
    const float* trans  = (const float*)d_in[3];
    const float* startt = (const float*)d_in[4];
    const float* endt   = (const float*)d_in[5];

    int B = out_size;                 // 256
    int T = in_sizes[0] / (B * 8);    // 16384 (= KCH * L)

    int nblocks = B * (KCH / CPB);    // 512
    crf_chunk_vec<<<nblocks, CPB>>>(em, tags, mask, trans, startt, B, T);

    crf_final<<<(B * 32 + 255) / 256, 256>>>(em, tags, mask, startt, endt,
                                             (float*)d_out, B, T);
}

// round 15
// speedup vs baseline: 1.1982x; 1.1762x over previous
#include <cuda_runtime.h>

#define L    64      // steps per chunk
#define KCH  256     // chunks per batch (T / L)
#define MAXB 256
#define OVLG 2       // overlap groups (8 warm-up steps)
#define CPB  128     // threads per block (= 64 chunks, 2 lanes each)
#define CPBC 64      // chunks per block
#define RS   36      // smem row stride in floats (32 data + 4 pad)

__device__ float g_c  [MAXB * KCH];
__device__ float g_sp [MAXB * KCH];
__device__ int   g_cnt[MAXB * KCH];
__device__ float g_nf [MAXB * 8];

// ---- packed f32x2 helpers ---------------------------------------------------
__device__ __forceinline__ unsigned long long pk2(float lo, float hi) {
    unsigned long long r;
    asm("mov.b64 %0, {%1, %2};" : "=l"(r) : "f"(lo), "f"(hi));
    return r;
}
__device__ __forceinline__ void upk2(unsigned long long v, float& lo, float& hi) {
    asm("mov.b64 {%0, %1}, %2;" : "=f"(lo), "=f"(hi) : "l"(v));
}
__device__ __forceinline__ unsigned long long mul2(unsigned long long a, unsigned long long b) {
    unsigned long long r;
    asm("mul.rn.f32x2 %0, %1, %2;" : "=l"(r) : "l"(a), "l"(b));
    return r;
}
__device__ __forceinline__ unsigned long long fma2(unsigned long long a, unsigned long long b,
                                                   unsigned long long c) {
    unsigned long long r;
    asm("fma.rn.f32x2 %0, %1, %2, %3;" : "=l"(r) : "l"(a), "l"(b), "l"(c));
    return r;
}

// ---------------------------------------------------------------------------
// One pair-split CRF step. Lane h owns global output columns [4h, 4h+4).
// v is in LOCAL order: v[0..3] = own half, v[4..7] = partner half
// (local slot li <-> global index (4h+li)&7; M2loc rows pre-permuted to match).
// Branch-uniform: always computes, commits under mk, then exchanges.
// ---------------------------------------------------------------------------
__device__ __forceinline__ void pstep(
    float v[8], const unsigned long long M2loc[8][2],
    float e0, float e1, float e2, float e3, int mk)
{
    const unsigned FULL = 0xffffffffu;
    unsigned long long ev0 = pk2(__expf(e0), __expf(e1));
    unsigned long long ev1 = pk2(__expf(e2), __expf(e3));

    unsigned long long vb = pk2(v[0], v[0]);
    unsigned long long a0 = mul2(vb, M2loc[0][0]);
    unsigned long long a1 = mul2(vb, M2loc[0][1]);
#pragma unroll
    for (int i = 1; i < 8; i++) {
        vb = pk2(v[i], v[i]);
        a0 = fma2(vb, M2loc[i][0], a0);
        a1 = fma2(vb, M2loc[i][1], a1);
    }
    a0 = mul2(a0, ev0);
    a1 = mul2(a1, ev1);
    float n0, n1, n2, n3;
    upk2(a0, n0, n1);
    upk2(a1, n2, n3);
    // commit under mask BEFORE exchange (partner does the same)
    n0 = mk ? n0 : v[0];
    n1 = mk ? n1 : v[1];
    n2 = mk ? n2 : v[2];
    n3 = mk ? n3 : v[3];
    v[0] = n0; v[1] = n1; v[2] = n2; v[3] = n3;
    v[4] = __shfl_xor_sync(FULL, n0, 1);
    v[5] = __shfl_xor_sync(FULL, n1, 1);
    v[6] = __shfl_xor_sync(FULL, n2, 1);
    v[7] = __shfl_xor_sync(FULL, n3, 1);
}

// ---------------------------------------------------------------------------
// Kernel 1: lane pair = chunk. Vector recurrence, 8-step warm-up, double-
// buffered LDG->reg->STS staging (pair-shared), fused score.
// ---------------------------------------------------------------------------
__global__ void __launch_bounds__(CPB) crf_chunk_pair(
    const float* __restrict__ em,
    const int* __restrict__ tags,
    const int* __restrict__ mask,
    const float* __restrict__ trans,
    const float* __restrict__ startt,
    int B, int T)
{
    __shared__ float sE[2][CPBC * RS];

    int tid = threadIdx.x;
    int b   = blockIdx.x >> 2;
    int k0  = (blockIdx.x & 3) * CPBC;
    int p   = tid >> 1;          // pair (chunk within block)
    int h   = tid & 1;           // half
    int k   = k0 + p;            // chunk index in batch
    size_t bT = (size_t)b * T;
    const float* emB = em + bT * 8;
    const unsigned FULL = 0xffffffffu;

    // M2loc[i][jj] = pk2(exp(Tr[gi][4h+2jj]), exp(Tr[gi][4h+2jj+1])), gi=(4h+i)&7
    unsigned long long M2loc[8][2];
#pragma unroll
    for (int i = 0; i < 8; i++) {
        int gi = (4 * h + i) & 7;
#pragma unroll
        for (int jj = 0; jj < 2; jj++)
            M2loc[i][jj] = pk2(__expf(__ldg(&trans[gi * 8 + 4 * h + 2 * jj])),
                               __expf(__ldg(&trans[gi * 8 + 4 * h + 2 * jj + 1])));
    }

    float v[8];
#pragma unroll
    for (int j = 0; j < 8; j++) v[j] = 0.125f;

    float c = 0.0f, sp = 0.0f;
    int mcnt = 0;
    int pv = __ldg(&tags[bT + (k > 0 ? k * L - 1 : 0)]);

    // staging: 4 float4 per thread covers 64 rows x 8 float4
    float4 stg[4];
#pragma unroll
    for (int m = 0; m < 4; m++) {
        int idx = m * CPB + tid;
        int r   = idx >> 3;
        int qq  = idx & 7;
        int tr  = (k0 + r) * L + 4 * (-OVLG);
        if (tr < 0) tr = 0;
        stg[m] = __ldg((const float4*)(emB + (size_t)tr * 8) + qq);
    }
#pragma unroll
    for (int m = 0; m < 4; m++) {
        int idx = m * CPB + tid;
        *((float4*)(sE[0] + (idx >> 3) * RS) + (idx & 7)) = stg[m];
    }
    __syncthreads();

    // tags/mask pair-cooperative prefetch for first group
    int4 rawn;
    {
        int tb = k * L + 4 * (-OVLG);
        int tc = tb < 0 ? 0 : tb;
        rawn = h ? __ldg((const int4*)(mask + bT + tc))
                 : __ldg((const int4*)(tags + bT + tc));
    }

    for (int g = -OVLG; g < L / 4; g++) {
        int cur = (g + OVLG) & 1;

        int4 raw = rawn;
        int4 oth;
        oth.x = __shfl_xor_sync(FULL, raw.x, 1);
        oth.y = __shfl_xor_sync(FULL, raw.y, 1);
        oth.z = __shfl_xor_sync(FULL, raw.z, 1);
        oth.w = __shfl_xor_sync(FULL, raw.w, 1);
        int4 tg4 = h ? oth : raw;
        int4 mk4 = h ? raw : oth;

        bool more = (g + 1 < L / 4);
        if (more) {
#pragma unroll
            for (int m = 0; m < 4; m++) {
                int idx = m * CPB + tid;
                int r   = idx >> 3;
                int qq  = idx & 7;
                int tr  = (k0 + r) * L + 4 * (g + 1);
                if (tr < 0) tr = 0;
                stg[m] = __ldg((const float4*)(emB + (size_t)tr * 8) + qq);
            }
            int tb = k * L + 4 * (g + 1);
            int tc = tb < 0 ? 0 : tb;
            rawn = h ? __ldg((const int4*)(mask + bT + tc))
                     : __ldg((const int4*)(tags + bT + tc));
        }

        int tb = k * L + 4 * g;
        const float* erow = sE[cur] + p * RS;

        if (g == 0) {
            if (k == 0) {
                // exact alpha0 in LOCAL order (full row: two float4 of step 0)
                float ef[8];
                *(float4*)(ef)     = *((const float4*)erow);
                *(float4*)(ef + 4) = *((const float4*)erow + 1);
                float s = 0.0f;
                float nv[8];
#pragma unroll
                for (int li = 0; li < 8; li++) {
                    int gl = (4 * h + li) & 7;
                    nv[li] = __expf(__ldg(&startt[gl]) + ef[gl]);
                    s += nv[li];
                }
#pragma unroll
                for (int li = 0; li < 8; li++) v[li] = nv[li];
                c = __logf(s);
                float r = __fdividef(1.0f, s);
#pragma unroll
                for (int j = 0; j < 8; j++) v[j] *= r;
            } else {
                float s = v[0]+v[1]+v[2]+v[3]+v[4]+v[5]+v[6]+v[7];
                float r = __fdividef(1.0f, s);
                c = 0.0f;
#pragma unroll
                for (int j = 0; j < 8; j++) v[j] *= r;
            }
        }

        {
            int tgA[4] = {tg4.x, tg4.y, tg4.z, tg4.w};
            int mkA[4] = {mk4.x, mk4.y, mk4.z, mk4.w};
#pragma unroll
            for (int q = 0; q < 4; q++) {
                // own half of this step's emission row (global cols 4h..4h+3)
                float4 eo = *((const float4*)(erow + q * 8 + 4 * h));
                int valid = (g >= 0) ? (mkA[q] && (tb + q >= 1))
                                     : ((tb >= 0) && mkA[q]);
                pstep(v, M2loc, eo.x, eo.y, eo.z, eo.w, valid);
                if (g >= 0) {
                    int tg = tgA[q];
                    if (valid) {
                        if ((tg >> 2) == h) {   // tag in my half: add score
                            float es = eo.x;
                            es = (tg & 3) == 1 ? eo.y : es;
                            es = (tg & 3) == 2 ? eo.z : es;
                            es = (tg & 3) == 3 ? eo.w : es;
                            sp += es + __ldg(&trans[pv * 8 + tg]);
                        }
                        if (h == 0) mcnt++;
                    }
                    pv = tg;
                }
            }
        }

        // group-end rescale (local order irrelevant for the sum)
        {
            float s = v[0]+v[1]+v[2]+v[3]+v[4]+v[5]+v[6]+v[7];
            float r = __fdividef(1.0f, s);
            c += __logf(s);
#pragma unroll
            for (int j = 0; j < 8; j++) v[j] *= r;
        }

        if (more) {
#pragma unroll
            for (int m = 0; m < 4; m++) {
                int idx = m * CPB + tid;
                *((float4*)(sE[cur ^ 1] + (idx >> 3) * RS) + (idx & 7)) = stg[m];
            }
            __syncthreads();
        }
    }

    // combine pair score; lane 0 (local order == global) stores results
    float sp_tot = sp + __shfl_xor_sync(FULL, sp, 1);
    if (h == 0) {
        size_t gidx = (size_t)b * KCH + k;
        g_c  [gidx] = c;
        g_sp [gidx] = sp_tot;
        g_cnt[gidx] = mcnt;
        if (k == KCH - 1) {
#pragma unroll
            for (int j = 0; j < 8; j++) g_nf[b * 8 + j] = v[j];
        }
    }
}

// ---------------------------------------------------------------------------
// Kernel 2: warp per batch (unchanged champion finalize).
// ---------------------------------------------------------------------------
__global__ void __launch_bounds__(256) crf_final(
    const float* __restrict__ em,
    const int* __restrict__ tags,
    const int* __restrict__ mask,
    const float* __restrict__ startt,
    const float* __restrict__ endt,
    float* __restrict__ out,
    int B, int T)
{
    int w    = (blockIdx.x * blockDim.x + threadIdx.x) >> 5;
    int lane = threadIdx.x & 31;
    if (w >= B) return;
    const int b = w;
    const unsigned FULL = 0xffffffffu;
    size_t bK = (size_t)b * KCH;

    float c = 0.0f, sp = 0.0f;
    int cnt = 0;
#pragma unroll
    for (int q = 0; q < 8; q++) {
        c   += __ldg(&g_c  [bK + lane + 32 * q]);
        sp  += __ldg(&g_sp [bK + lane + 32 * q]);
        cnt += __ldg(&g_cnt[bK + lane + 32 * q]);
    }
#pragma unroll
    for (int off = 16; off >= 1; off >>= 1) {
        c   += __shfl_xor_sync(FULL, c,   off);
        sp  += __shfl_xor_sync(FULL, sp,  off);
        cnt += __shfl_xor_sync(FULL, cnt, off);
    }

    if (lane == 0) {
        size_t bT = (size_t)b * T;
        float vsum = 0.0f;
#pragma unroll
        for (int j = 0; j < 8; j++)
            vsum += g_nf[b * 8 + j] * __expf(__ldg(&endt[j]));
        float logZ = c + __logf(vsum);

        cnt += (__ldg(&mask[bT]) != 0) ? 1 : 0;
        int last_valid = cnt - 1;
        int tag0  = __ldg(&tags[bT]);
        int lastt = __ldg(&tags[bT + last_valid]);
        float score = __ldg(&startt[tag0]) + __ldg(&em[bT * 8 + tag0])
                    + sp + __ldg(&endt[lastt]);
        out[b] = logZ - score;
    }
}

// ---------------------------------------------------------------------------
extern "C" void kernel_launch(void* const* d_in, const int* in_sizes, int n_in,
                              void* d_out, int out_size)
{
    const float* em     = (const float*)d_in[0];
    const int*   tags   = (const int*)d_in[1];
    const int*   mask   = (const int*)d_in[2];
    const float* trans  = (const float*)d_in[3];
    const float* startt = (const float*)d_in[4];
    const float* endt   = (const float*)d_in[5];

    int B = out_size;                 // 256
    int T = in_sizes[0] / (B * 8);    // 16384 (= KCH * L)

    int nblocks = B * (KCH / CPBC);   // 1024
    crf_chunk_pair<<<nblocks, CPB>>>(em, tags, mask, trans, startt, B, T);

    crf_final<<<(B * 32 + 255) / 256, 256>>>(em, tags, mask, startt, endt,
                                             (float*)d_out, B, T);
}

// round 16
// speedup vs baseline: 1.2392x; 1.0342x over previous
#include <cuda_runtime.h>

#define L    64      // steps per chunk
#define KCH  256     // chunks per batch (T / L)
#define MAXB 256
#define OVLG 2       // overlap groups (8 warm-up steps)
#define CPB  128     // threads per block (= 64 chunks, 2 lanes each)
#define CPBC 64      // chunks per block
#define RS   36      // smem row stride in floats (32 data + 4 pad)

__device__ float g_c  [MAXB * KCH];
__device__ float g_sp [MAXB * KCH];
__device__ int   g_cnt[MAXB * KCH];
__device__ float g_nf [MAXB * 8];

// ---- packed f32x2 helpers ---------------------------------------------------
__device__ __forceinline__ unsigned long long pk2(float lo, float hi) {
    unsigned long long r;
    asm("mov.b64 %0, {%1, %2};" : "=l"(r) : "f"(lo), "f"(hi));
    return r;
}
__device__ __forceinline__ void upk2(unsigned long long v, float& lo, float& hi) {
    asm("mov.b64 {%0, %1}, %2;" : "=f"(lo), "=f"(hi) : "l"(v));
}
__device__ __forceinline__ unsigned long long mul2(unsigned long long a, unsigned long long b) {
    unsigned long long r;
    asm("mul.rn.f32x2 %0, %1, %2;" : "=l"(r) : "l"(a), "l"(b));
    return r;
}
__device__ __forceinline__ unsigned long long add2(unsigned long long a, unsigned long long b) {
    unsigned long long r;
    asm("add.rn.f32x2 %0, %1, %2;" : "=l"(r) : "l"(a), "l"(b));
    return r;
}
__device__ __forceinline__ unsigned long long fma2(unsigned long long a, unsigned long long b,
                                                   unsigned long long c) {
    unsigned long long r;
    asm("fma.rn.f32x2 %0, %1, %2, %3;" : "=l"(r) : "l"(a), "l"(b), "l"(c));
    return r;
}

// ---------------------------------------------------------------------------
// One pair-split CRF step, even/odd split dot chains (4-deep + add).
// Lane h owns global output columns [4h, 4h+4); v in LOCAL order.
// Branch-uniform: always computes, commits under mk, then exchanges.
// ---------------------------------------------------------------------------
__device__ __forceinline__ void pstep(
    float v[8], const unsigned long long M2loc[8][2],
    float e0, float e1, float e2, float e3, int mk)
{
    const unsigned FULL = 0xffffffffu;
    unsigned long long ev0 = pk2(__expf(e0), __expf(e1));
    unsigned long long ev1 = pk2(__expf(e2), __expf(e3));

    unsigned long long vb0 = pk2(v[0], v[0]);
    unsigned long long vb1 = pk2(v[1], v[1]);
    unsigned long long a0e = mul2(vb0, M2loc[0][0]);
    unsigned long long a1e = mul2(vb0, M2loc[0][1]);
    unsigned long long a0o = mul2(vb1, M2loc[1][0]);
    unsigned long long a1o = mul2(vb1, M2loc[1][1]);
#pragma unroll
    for (int i = 2; i < 8; i += 2) {
        unsigned long long be = pk2(v[i],     v[i]);
        unsigned long long bo = pk2(v[i + 1], v[i + 1]);
        a0e = fma2(be, M2loc[i][0],     a0e);
        a1e = fma2(be, M2loc[i][1],     a1e);
        a0o = fma2(bo, M2loc[i + 1][0], a0o);
        a1o = fma2(bo, M2loc[i + 1][1], a1o);
    }
    unsigned long long a0 = mul2(add2(a0e, a0o), ev0);
    unsigned long long a1 = mul2(add2(a1e, a1o), ev1);
    float n0, n1, n2, n3;
    upk2(a0, n0, n1);
    upk2(a1, n2, n3);
    n0 = mk ? n0 : v[0];
    n1 = mk ? n1 : v[1];
    n2 = mk ? n2 : v[2];
    n3 = mk ? n3 : v[3];
    v[0] = n0; v[1] = n1; v[2] = n2; v[3] = n3;
    v[4] = __shfl_xor_sync(FULL, n0, 1);
    v[5] = __shfl_xor_sync(FULL, n1, 1);
    v[6] = __shfl_xor_sync(FULL, n2, 1);
    v[7] = __shfl_xor_sync(FULL, n3, 1);
}

// ---------------------------------------------------------------------------
// Kernel 1: lane pair = chunk. Vector recurrence, 8-step warm-up, double-
// buffered LDG->reg->STS staging (pair-shared), fused score.
// ---------------------------------------------------------------------------
__global__ void __launch_bounds__(CPB, 4) crf_chunk_pair(
    const float* __restrict__ em,
    const int* __restrict__ tags,
    const int* __restrict__ mask,
    const float* __restrict__ trans,
    const float* __restrict__ startt,
    int B, int T)
{
    __shared__ float sE[2][CPBC * RS];

    int tid = threadIdx.x;
    int b   = blockIdx.x >> 2;
    int k0  = (blockIdx.x & 3) * CPBC;
    int p   = tid >> 1;          // pair (chunk within block)
    int h   = tid & 1;           // half
    int k   = k0 + p;            // chunk index in batch
    size_t bT = (size_t)b * T;
    const float* emB = em + bT * 8;
    const unsigned FULL = 0xffffffffu;

    // M2loc[i][jj] = pk2(exp(Tr[gi][4h+2jj]), exp(Tr[gi][4h+2jj+1])), gi=(4h+i)&7
    unsigned long long M2loc[8][2];
#pragma unroll
    for (int i = 0; i < 8; i++) {
        int gi = (4 * h + i) & 7;
#pragma unroll
        for (int jj = 0; jj < 2; jj++)
            M2loc[i][jj] = pk2(__expf(__ldg(&trans[gi * 8 + 4 * h + 2 * jj])),
                               __expf(__ldg(&trans[gi * 8 + 4 * h + 2 * jj + 1])));
    }

    float v[8];
#pragma unroll
    for (int j = 0; j < 8; j++) v[j] = 0.125f;

    float c = 0.0f, sp = 0.0f;
    int mcnt = 0;
    int pv = __ldg(&tags[bT + (k > 0 ? k * L - 1 : 0)]);

    // staging: 4 float4 per thread covers 64 rows x 8 float4
    float4 stg[4];
#pragma unroll
    for (int m = 0; m < 4; m++) {
        int idx = m * CPB + tid;
        int r   = idx >> 3;
        int qq  = idx & 7;
        int tr  = (k0 + r) * L + 4 * (-OVLG);
        if (tr < 0) tr = 0;
        stg[m] = __ldg((const float4*)(emB + (size_t)tr * 8) + qq);
    }
#pragma unroll
    for (int m = 0; m < 4; m++) {
        int idx = m * CPB + tid;
        *((float4*)(sE[0] + (idx >> 3) * RS) + (idx & 7)) = stg[m];
    }
    __syncthreads();

    // tags/mask pair-cooperative prefetch for first group
    int4 rawn;
    {
        int tb = k * L + 4 * (-OVLG);
        int tc = tb < 0 ? 0 : tb;
        rawn = h ? __ldg((const int4*)(mask + bT + tc))
                 : __ldg((const int4*)(tags + bT + tc));
    }

    for (int g = -OVLG; g < L / 4; g++) {
        int cur = (g + OVLG) & 1;

        int4 raw = rawn;
        int4 oth;
        oth.x = __shfl_xor_sync(FULL, raw.x, 1);
        oth.y = __shfl_xor_sync(FULL, raw.y, 1);
        oth.z = __shfl_xor_sync(FULL, raw.z, 1);
        oth.w = __shfl_xor_sync(FULL, raw.w, 1);
        int4 tg4 = h ? oth : raw;
        int4 mk4 = h ? raw : oth;

        bool more = (g + 1 < L / 4);
        if (more) {
#pragma unroll
            for (int m = 0; m < 4; m++) {
                int idx = m * CPB + tid;
                int r   = idx >> 3;
                int qq  = idx & 7;
                int tr  = (k0 + r) * L + 4 * (g + 1);
                if (tr < 0) tr = 0;
                stg[m] = __ldg((const float4*)(emB + (size_t)tr * 8) + qq);
            }
            int tb = k * L + 4 * (g + 1);
            int tc = tb < 0 ? 0 : tb;
            rawn = h ? __ldg((const int4*)(mask + bT + tc))
                     : __ldg((const int4*)(tags + bT + tc));
        }

        int tb = k * L + 4 * g;
        const float* erow = sE[cur] + p * RS;

        if (g == 0) {
            if (k == 0) {
                // exact alpha0 in LOCAL order
                float ef[8];
                *(float4*)(ef)     = *((const float4*)erow);
                *(float4*)(ef + 4) = *((const float4*)erow + 1);
                float s = 0.0f;
                float nv[8];
#pragma unroll
                for (int li = 0; li < 8; li++) {
                    int gl = (4 * h + li) & 7;
                    nv[li] = __expf(__ldg(&startt[gl]) + ef[gl]);
                    s += nv[li];
                }
#pragma unroll
                for (int li = 0; li < 8; li++) v[li] = nv[li];
                c = __logf(s);
                float r = __fdividef(1.0f, s);
#pragma unroll
                for (int j = 0; j < 8; j++) v[j] *= r;
            } else {
                float s = v[0]+v[1]+v[2]+v[3]+v[4]+v[5]+v[6]+v[7];
                float r = __fdividef(1.0f, s);
                c = 0.0f;
#pragma unroll
                for (int j = 0; j < 8; j++) v[j] *= r;
            }
        }

        {
            int tgA[4] = {tg4.x, tg4.y, tg4.z, tg4.w};
            int mkA[4] = {mk4.x, mk4.y, mk4.z, mk4.w};
#pragma unroll
            for (int q = 0; q < 4; q++) {
                float4 eo = *((const float4*)(erow + q * 8 + 4 * h));
                int valid = (g >= 0) ? (mkA[q] && (tb + q >= 1))
                                     : ((tb >= 0) && mkA[q]);
                pstep(v, M2loc, eo.x, eo.y, eo.z, eo.w, valid);
                if (g >= 0) {
                    int tg = tgA[q];
                    if (valid) {
                        if ((tg >> 2) == h) {
                            float es = eo.x;
                            es = (tg & 3) == 1 ? eo.y : es;
                            es = (tg & 3) == 2 ? eo.z : es;
                            es = (tg & 3) == 3 ? eo.w : es;
                            sp += es + __ldg(&trans[pv * 8 + tg]);
                        }
                        if (h == 0) mcnt++;
                    }
                    pv = tg;
                }
            }
        }

        // group-end rescale
        {
            float s = v[0]+v[1]+v[2]+v[3]+v[4]+v[5]+v[6]+v[7];
            float r = __fdividef(1.0f, s);
            c += __logf(s);
#pragma unroll
            for (int j = 0; j < 8; j++) v[j] *= r;
        }

        if (more) {
#pragma unroll
            for (int m = 0; m < 4; m++) {
                int idx = m * CPB + tid;
                *((float4*)(sE[cur ^ 1] + (idx >> 3) * RS) + (idx & 7)) = stg[m];
            }
            __syncthreads();
        }
    }

    float sp_tot = sp + __shfl_xor_sync(FULL, sp, 1);
    if (h == 0) {
        size_t gidx = (size_t)b * KCH + k;
        g_c  [gidx] = c;
        g_sp [gidx] = sp_tot;
        g_cnt[gidx] = mcnt;
        if (k == KCH - 1) {
#pragma unroll
            for (int j = 0; j < 8; j++) g_nf[b * 8 + j] = v[j];
        }
    }
}

// ---------------------------------------------------------------------------
// Kernel 2: warp per batch (unchanged champion finalize).
// ---------------------------------------------------------------------------
__global__ void __launch_bounds__(256) crf_final(
    const float* __restrict__ em,
    const int* __restrict__ tags,
    const int* __restrict__ mask,
    const float* __restrict__ startt,
    const float* __restrict__ endt,
    float* __restrict__ out,
    int B, int T)
{
    int w    = (blockIdx.x * blockDim.x + threadIdx.x) >> 5;
    int lane = threadIdx.x & 31;
    if (w >= B) return;
    const int b = w;
    const unsigned FULL = 0xffffffffu;
    size_t bK = (size_t)b * KCH;

    float c = 0.0f, sp = 0.0f;
    int cnt = 0;
#pragma unroll
    for (int q = 0; q < 8; q++) {
        c   += __ldg(&g_c  [bK + lane + 32 * q]);
        sp  += __ldg(&g_sp [bK + lane + 32 * q]);
        cnt += __ldg(&g_cnt[bK + lane + 32 * q]);
    }
#pragma unroll
    for (int off = 16; off >= 1; off >>= 1) {
        c   += __shfl_xor_sync(FULL, c,   off);
        sp  += __shfl_xor_sync(FULL, sp,  off);
        cnt += __shfl_xor_sync(FULL, cnt, off);
    }

    if (lane == 0) {
        size_t bT = (size_t)b * T;
        float vsum = 0.0f;
#pragma unroll
        for (int j = 0; j < 8; j++)
            vsum += g_nf[b * 8 + j] * __expf(__ldg(&endt[j]));
        float logZ = c + __logf(vsum);

        cnt += (__ldg(&mask[bT]) != 0) ? 1 : 0;
        int last_valid = cnt - 1;
        int tag0  = __ldg(&tags[bT]);
        int lastt = __ldg(&tags[bT + last_valid]);
        float score = __ldg(&startt[tag0]) + __ldg(&em[bT * 8 + tag0])
                    + sp + __ldg(&endt[lastt]);
        out[b] = logZ - score;
    }
}

// ---------------------------------------------------------------------------
extern "C" void kernel_launch(void* const* d_in, const int* in_sizes, int n_in,
                              void* d_out, int out_size)
{
    const float* em     = (const float*)d_in[0];
    const int*   tags   = (const int*)d_in[1];
    const int*   mask   = (const int*)d_in[2];
    const float* trans  = (const float*)d_in[3];
    const float* startt = (const float*)d_in[4];
    const float* endt   = (const float*)d_in[5];

    int B = out_size;                 // 256
    int T = in_sizes[0] / (B * 8);    // 16384 (= KCH * L)

    int nblocks = B * (KCH / CPBC);   // 1024
    crf_chunk_pair<<<nblocks, CPB>>>(em, tags, mask, trans, startt, B, T);

    crf_final<<<(B * 32 + 255) / 256, 256>>>(em, tags, mask, startt, endt,
                                             (float*)d_out, B, T);
}